// round 8
// baseline (speedup 1.0000x reference)
#include <cuda_runtime.h>
#include <math.h>
#include <stdint.h>

#define TT 256
#define BB 64
#define DD 1024
#define ND 3072          // 3*D
#define MM (TT*BB)       // 16384
#define NBLK 64          // scan blocks; each owns 16 d-cols

// ---------------- device scratch (no cudaMalloc allowed) -------------------
__device__ __align__(16) float  g_xproj[(size_t)MM * ND];   // [T*B, 3D]
__device__ __align__(16) float  g_ins32[(size_t)MM * DD];   // tf32-rounded ins
__device__ __align__(16) float  g_Wi32[(size_t)DD * ND];    // tf32-rounded W_i
__device__ __align__(16) float  g_hx[2][BB * DD];           // exact h_eff ping-pong
__device__ float4               g_hf[2][BB * DD / 4];       // frag-ordered tf32 h ping-pong
__device__ unsigned             g_ctr;                      // grid barrier counter

__device__ __forceinline__ float to_tf32(float x) {
    float y;
    asm("cvt.rna.tf32.f32 %0, %1;" : "=f"(y) : "f"(x));
    return y;
}

__device__ __forceinline__ void mma_au(float d[4], const unsigned a[4],
                                       unsigned b0, unsigned b1) {
    asm volatile("mma.sync.aligned.m16n8k8.row.col.f32.tf32.tf32.f32 "
                 "{%0,%1,%2,%3}, {%4,%5,%6,%7}, {%8,%9}, {%0,%1,%2,%3};"
                 : "+f"(d[0]), "+f"(d[1]), "+f"(d[2]), "+f"(d[3])
                 : "r"(a[0]), "r"(a[1]), "r"(a[2]), "r"(a[3]),
                   "r"(b0), "r"(b1));
}

__device__ __forceinline__ void mma_f4(float d[4], const float4& a, const float2& b) {
    unsigned av[4] = {__float_as_uint(a.x), __float_as_uint(a.y),
                      __float_as_uint(a.z), __float_as_uint(a.w)};
    mma_au(d, av, __float_as_uint(b.x), __float_as_uint(b.y));
}

__device__ __forceinline__ void cp16(const void* smem_dst, const float* src) {
    unsigned d = (unsigned)__cvta_generic_to_shared(smem_dst);
    asm volatile("cp.async.cg.shared.global [%0], [%1], 16;" :: "r"(d), "l"(src));
}
__device__ __forceinline__ void cp_commit() {
    asm volatile("cp.async.commit_group;" ::: "memory");
}

// frag-order offset (floats) of h[b][k] inside one g_hf buffer:
// layout [ks(128)][mt(4)][lane(32)] float4
__device__ __forceinline__ int frag_off(int b, int k) {
    int mt = b >> 4, r = b & 15, q = r & 7, rh = r >> 3;
    int ks = k >> 3, kk = k & 7, tg = kk & 3, khf = kk >> 2;
    return (((ks * 4 + mt) * 32) + (q * 4 + tg)) * 4 + (rh + 2 * khf);
}

// ---------------------------------------------------------------------------
// prep: tf32-round ins + W_i; build step-0 h (done-masked) exact + frag; ctr=0
// ---------------------------------------------------------------------------
__global__ void prep(const float* __restrict__ ins,
                     const float* __restrict__ W_i,
                     const float* __restrict__ hiddens,
                     const int*   __restrict__ dones,
                     const float* __restrict__ init_carry) {
    size_t i0 = (size_t)blockIdx.x * blockDim.x + threadIdx.x;
    size_t stride = (size_t)gridDim.x * blockDim.x;

    const float4* s1 = (const float4*)ins;
    float4* d1 = (float4*)g_ins32;
    for (size_t i = i0; i < (size_t)MM * DD / 4; i += stride) {
        float4 v = s1[i];
        v.x = to_tf32(v.x); v.y = to_tf32(v.y);
        v.z = to_tf32(v.z); v.w = to_tf32(v.w);
        d1[i] = v;
    }
    const float4* s2 = (const float4*)W_i;
    float4* d2 = (float4*)g_Wi32;
    for (size_t i = i0; i < (size_t)DD * ND / 4; i += stride) {
        float4 v = s2[i];
        v.x = to_tf32(v.x); v.y = to_tf32(v.y);
        v.z = to_tf32(v.z); v.w = to_tf32(v.w);
        d2[i] = v;
    }
    for (size_t i = i0; i < (size_t)BB * DD; i += stride) {
        int b = (int)(i >> 10), d = (int)(i & 1023);
        float v = dones[b] ? hiddens[i] : init_carry[i];
        g_hx[0][i] = v;
        ((float*)g_hf[0])[frag_off(b, d)] = to_tf32(v);
    }
    if (i0 == 0) g_ctr = 0u;
}

// ---------------------------------------------------------------------------
// x_proj GEMM: C = g_ins32 * g_Wi32 + b_i.  128x128 tile, BK=32, cp.async
// double-buffered. 256 thr = 8 warps (2 wm x 4 wn), warp tile 64x32.
// ---------------------------------------------------------------------------
#define GA_ST 4608   // 128*36 floats per A stage
#define GB_ST 4224   // 32*132 floats per B stage
#define GEMM_SMEM ((2*GA_ST + 2*GB_ST) * 4)

__global__ void __launch_bounds__(256, 1)
gemm_xproj(const float* __restrict__ bias) {
    extern __shared__ float sm[];
    float* As = sm;
    float* Bs = sm + 2 * GA_ST;

    const int tid  = threadIdx.x;
    const int w    = tid >> 5, lane = tid & 31;
    const int q    = lane >> 2, tg = lane & 3;
    const int wm   = w >> 2, wn = w & 3;
    const int bm   = blockIdx.y * 128;
    const int bn   = blockIdx.x * 128;

    float acc[16][4];
    #pragma unroll
    for (int i = 0; i < 16; i++)
        #pragma unroll
        for (int j = 0; j < 4; j++) acc[i][j] = 0.f;

    #define LOAD_STAGE(st, kc)                                                  \
    {                                                                           \
        _Pragma("unroll")                                                       \
        for (int l = 0; l < 4; l++) {                                           \
            int e = tid + l * 256; int r = e >> 3, c4 = e & 7;                  \
            cp16(&As[(st) * GA_ST + r * 36 + c4 * 4],                           \
                 &g_ins32[(size_t)(bm + r) * DD + (kc) + c4 * 4]);              \
        }                                                                       \
        _Pragma("unroll")                                                       \
        for (int l = 0; l < 4; l++) {                                           \
            int e = tid + l * 256; int r = e >> 5, c4 = e & 31;                 \
            cp16(&Bs[(st) * GB_ST + r * 132 + c4 * 4],                          \
                 &g_Wi32[(size_t)((kc) + r) * ND + bn + c4 * 4]);               \
        }                                                                       \
        cp_commit();                                                            \
    }

    LOAD_STAGE(0, 0)

    for (int itk = 0; itk < DD / 32; itk++) {
        if (itk + 1 < DD / 32) {
            LOAD_STAGE((itk + 1) & 1, (itk + 1) * 32)
            asm volatile("cp.async.wait_group 1;" ::: "memory");
        } else {
            asm volatile("cp.async.wait_group 0;" ::: "memory");
        }
        __syncthreads();

        const float* as = &As[(itk & 1) * GA_ST];
        const float* bs = &Bs[(itk & 1) * GB_ST];

        #pragma unroll
        for (int ks = 0; ks < 4; ks++) {
            const int koff = ks * 8;
            unsigned a[4][4];
            #pragma unroll
            for (int mt = 0; mt < 4; mt++) {
                int r0 = wm * 64 + mt * 16 + q;
                a[mt][0] = __float_as_uint(as[r0 * 36 + koff + tg]);
                a[mt][1] = __float_as_uint(as[(r0 + 8) * 36 + koff + tg]);
                a[mt][2] = __float_as_uint(as[r0 * 36 + koff + tg + 4]);
                a[mt][3] = __float_as_uint(as[(r0 + 8) * 36 + koff + tg + 4]);
            }
            #pragma unroll
            for (int nt = 0; nt < 4; nt++) {
                int n = wn * 32 + nt * 8 + q;
                unsigned b0 = __float_as_uint(bs[(koff + tg) * 132 + n]);
                unsigned b1 = __float_as_uint(bs[(koff + tg + 4) * 132 + n]);
                #pragma unroll
                for (int mt = 0; mt < 4; mt++)
                    mma_au(acc[mt * 4 + nt], a[mt], b0, b1);
            }
        }
        __syncthreads();
    }

    #pragma unroll
    for (int mt = 0; mt < 4; mt++) {
        int row = bm + wm * 64 + mt * 16 + q;
        #pragma unroll
        for (int nt = 0; nt < 4; nt++) {
            int col = bn + wn * 32 + nt * 8 + 2 * tg;
            float2 bb = *(const float2*)&bias[col];
            float* c = acc[mt * 4 + nt];
            float2 v0 = make_float2(c[0] + bb.x, c[1] + bb.y);
            float2 v1 = make_float2(c[2] + bb.x, c[3] + bb.y);
            *(float2*)&g_xproj[(size_t)row * ND + col] = v0;
            *(float2*)&g_xproj[(size_t)(row + 8) * ND + col] = v1;
        }
    }
}

// ---------------------------------------------------------------------------
// Persistent GRU scan. grid=64 (1/SM), block=256. Block owns 16 d-cols
// (48 gate cols). W_h slice frag-ordered in smem (192KB). 8 warps = 4 kh x
// 2 mh: warp does 2 m-tiles x 6 n-tiles over its k-quarter (32 ksg).
// A-frags: direct LDG.128 (L2-only) from frag-ordered g_hf, depth-4 pipeline.
// 2-slab reduction, float4 epilogue, grid barrier per step.
//
// smem floats: Wf [ksg128][nt6][lane32]x2 = 49152 ; Red 2 x 64 x 48 = 6144
// ---------------------------------------------------------------------------
#define SCAN_SMEM ((49152 + 6144) * 4)

__global__ void __launch_bounds__(256, 1)
gru_scan(const float* __restrict__ hiddens,
         const int*   __restrict__ dones,
         const float* __restrict__ W_h,
         const float* __restrict__ b_hn,
         float* __restrict__ out) {
    extern __shared__ float smem[];
    float* Wf  = smem;             // 49152 floats
    float* Red = smem + 49152;     // 2 slabs x 3072 floats

    const int tid  = threadIdx.x;
    const int w    = tid >> 5;
    const int lane = tid & 31;
    const int q    = lane >> 2;
    const int tg   = lane & 3;
    const int kh   = w >> 1;            // k-quarter 0..3
    const int mh   = w & 1;             // m-half
    const int d0   = blockIdx.x * 16;

    // ---- one-time: build frag-ordered W (tf32), 48 gate cols ----
    for (int idx = tid; idx < 49152; idx += 256) {
        int hh = idx & 1, p = idx >> 1;
        int ln = p & 31, rest = p >> 5;
        int nt = rest % 6, ksg = rest / 6;
        int qq = ln >> 2, tt = ln & 3;
        int k  = ksg * 8 + tt + hh * 4;
        int g  = nt >> 1;
        int dc = d0 + (nt & 1) * 8 + qq;
        Wf[idx] = to_tf32(W_h[(size_t)k * ND + g * DD + dc]);
    }
    __syncthreads();

    // epilogue-fixed indices: thread owns (b=pb, d=pd..pd+3)
    const int pb  = tid >> 2;
    const int di0 = (tid & 3) * 4;
    const int pd  = d0 + di0;
    const float4 bh4 = *(const float4*)&b_hn[pd];
    int fo[4];
    #pragma unroll
    for (int j = 0; j < 4; j++) fo[j] = frag_off(pb, pd + j);

    const int ksgBase = kh * 32;

    for (int t = 0; t < TT; t++) {
        const int par = t & 1;

        // ---- early loads for epilogue (latency hidden under k-loop) ----
        size_t tb = (size_t)t * BB + pb;
        float4 xr = *(const float4*)&g_xproj[tb * ND + pd];
        float4 xz = *(const float4*)&g_xproj[tb * ND + DD + pd];
        float4 xn = *(const float4*)&g_xproj[tb * ND + 2 * DD + pd];
        float4 he = *(const float4*)&g_hx[par][pb * DD + pd];   // own write, L1 ok
        float4 hv = make_float4(0.f, 0.f, 0.f, 0.f);
        int dn = 0;
        if (t + 1 < TT) {
            hv = *(const float4*)&hiddens[((size_t)(t + 1) * BB + pb) * DD + pd];
            dn = dones[(t + 1) * BB + pb];
        }

        // ---- k loop: 32 ksg per warp, depth-4 LDG pipeline ----
        const float4* hf = g_hf[par];
        float4 pre[4][2];
        #pragma unroll
        for (int i = 0; i < 4; i++)
            #pragma unroll
            for (int m = 0; m < 2; m++)
                pre[i][m] = __ldcg(&hf[((ksgBase + i) * 4 + (mh * 2 + m)) * 32 + lane]);

        float acc[12][4];   // [m(2)*6 + nt]
        #pragma unroll
        for (int i = 0; i < 12; i++)
            #pragma unroll
            for (int j = 0; j < 4; j++) acc[i][j] = 0.f;

        const float2* Wf2 = (const float2*)Wf;
        #pragma unroll
        for (int it = 0; it < 32; it++) {
            const int slot = it & 3;
            #pragma unroll
            for (int nt = 0; nt < 6; nt++) {
                float2 bv = Wf2[((ksgBase + it) * 6 + nt) * 32 + lane];
                mma_f4(acc[0 * 6 + nt], pre[slot][0], bv);
                mma_f4(acc[1 * 6 + nt], pre[slot][1], bv);
            }
            if (it + 4 < 32) {
                #pragma unroll
                for (int m = 0; m < 2; m++)
                    pre[slot][m] = __ldcg(
                        &hf[((ksgBase + it + 4) * 4 + (mh * 2 + m)) * 32 + lane]);
            }
        }

        // ---- reduce 4 k-partials -> 2 slabs ----
        float* slab = &Red[(kh & 1) * 3072];
        if (kh >= 2) {
            #pragma unroll
            for (int m = 0; m < 2; m++)
                #pragma unroll
                for (int nt = 0; nt < 6; nt++) {
                    int row = (mh * 2 + m) * 16 + q;
                    int cb  = (nt >> 1) * 16 + (nt & 1) * 8 + 2 * tg;
                    float* c = acc[m * 6 + nt];
                    slab[row * 48 + cb]           = c[0];
                    slab[row * 48 + cb + 1]       = c[1];
                    slab[(row + 8) * 48 + cb]     = c[2];
                    slab[(row + 8) * 48 + cb + 1] = c[3];
                }
        }
        __syncthreads();
        if (kh < 2) {
            #pragma unroll
            for (int m = 0; m < 2; m++)
                #pragma unroll
                for (int nt = 0; nt < 6; nt++) {
                    int row = (mh * 2 + m) * 16 + q;
                    int cb  = (nt >> 1) * 16 + (nt & 1) * 8 + 2 * tg;
                    float* c = acc[m * 6 + nt];
                    slab[row * 48 + cb]           += c[0];
                    slab[row * 48 + cb + 1]       += c[1];
                    slab[(row + 8) * 48 + cb]     += c[2];
                    slab[(row + 8) * 48 + cb + 1] += c[3];
                }
        }
        __syncthreads();

        // ---- gate epilogue: 4 adjacent d per thread ----
        {
            float4 s0r = *(const float4*)&Red[pb * 48 + di0];
            float4 s0z = *(const float4*)&Red[pb * 48 + 16 + di0];
            float4 s0n = *(const float4*)&Red[pb * 48 + 32 + di0];
            float4 s1r = *(const float4*)&Red[3072 + pb * 48 + di0];
            float4 s1z = *(const float4*)&Red[3072 + pb * 48 + 16 + di0];
            float4 s1n = *(const float4*)&Red[3072 + pb * 48 + 32 + di0];

            float sr[4] = {s0r.x + s1r.x, s0r.y + s1r.y, s0r.z + s1r.z, s0r.w + s1r.w};
            float sz[4] = {s0z.x + s1z.x, s0z.y + s1z.y, s0z.z + s1z.z, s0z.w + s1z.w};
            float sn[4] = {s0n.x + s1n.x, s0n.y + s1n.y, s0n.z + s1n.z, s0n.w + s1n.w};
            float xrv[4] = {xr.x, xr.y, xr.z, xr.w};
            float xzv[4] = {xz.x, xz.y, xz.z, xz.w};
            float xnv[4] = {xn.x, xn.y, xn.z, xn.w};
            float hev[4] = {he.x, he.y, he.z, he.w};
            float bhv[4] = {bh4.x, bh4.y, bh4.z, bh4.w};
            float hvv[4] = {hv.x, hv.y, hv.z, hv.w};

            float h[4], v[4];
            #pragma unroll
            for (int j = 0; j < 4; j++) {
                float r = 1.f / (1.f + __expf(-(xrv[j] + sr[j])));
                float z = 1.f / (1.f + __expf(-(xzv[j] + sz[j])));
                float n = tanhf(xnv[j] + r * (sn[j] + bhv[j]));
                h[j] = (1.f - z) * n + z * hev[j];
                v[j] = dn ? hvv[j] : h[j];
            }

            *(float4*)&out[(size_t)BB * DD + tb * DD + pd] =
                make_float4(h[0], h[1], h[2], h[3]);
            if (t == TT - 1)
                *(float4*)&out[(size_t)pb * DD + pd] =
                    make_float4(h[0], h[1], h[2], h[3]);

            *(float4*)&g_hx[par ^ 1][pb * DD + pd] =
                make_float4(v[0], v[1], v[2], v[3]);
            float* hfn = (float*)g_hf[par ^ 1];
            #pragma unroll
            for (int j = 0; j < 4; j++) hfn[fo[j]] = to_tf32(v[j]);
        }

        // ---- grid barrier ----
        __threadfence();
        __syncthreads();
        if (tid == 0) {
            atomicAdd(&g_ctr, 1u);
            const unsigned target = (unsigned)(t + 1) * NBLK;
            unsigned vv;
            do {
                asm volatile("ld.acquire.gpu.global.u32 %0, [%1];"
                             : "=r"(vv) : "l"(&g_ctr) : "memory");
            } while (vv < target);
        }
        __syncthreads();
    }
}

// ---------------------------------------------------------------------------
extern "C" void kernel_launch(void* const* d_in, const int* in_sizes, int n_in,
                              void* d_out, int out_size) {
    const float* ins        = (const float*)d_in[0];
    const float* hiddens    = (const float*)d_in[1];
    const int*   dones      = (const int*)d_in[2];
    const float* init_carry = (const float*)d_in[3];
    const float* W_i        = (const float*)d_in[4];
    const float* W_h        = (const float*)d_in[5];
    const float* b_i        = (const float*)d_in[6];
    const float* b_hn       = (const float*)d_in[7];
    float* out = (float*)d_out;

    static int attr_set = 0;
    if (!attr_set) {
        cudaFuncSetAttribute(gemm_xproj, cudaFuncAttributeMaxDynamicSharedMemorySize,
                             GEMM_SMEM);
        cudaFuncSetAttribute(gru_scan, cudaFuncAttributeMaxDynamicSharedMemorySize,
                             SCAN_SMEM);
        attr_set = 1;
    }

    prep<<<2048, 256>>>(ins, W_i, hiddens, dones, init_carry);

    dim3 grid_gemm(ND / 128, MM / 128);   // 24 x 128
    gemm_xproj<<<grid_gemm, 256, GEMM_SMEM>>>(b_i);

    gru_scan<<<NBLK, 256, SCAN_SMEM>>>(hiddens, dones, W_h, b_hn, out);
}

// round 9
// speedup vs baseline: 1.1675x; 1.1675x over previous
#include <cuda_runtime.h>
#include <math.h>
#include <stdint.h>

#define TT 256
#define BB 64
#define DD 1024
#define ND 3072          // 3*D
#define MM (TT*BB)       // 16384
#define NBLK 128         // scan blocks; each owns 8 d-cols

// ---------------- device scratch (no cudaMalloc allowed) -------------------
__device__ __align__(16) float  g_xproj[(size_t)MM * ND];   // [T*B, 3D]
__device__ __align__(16) float  g_ins32[(size_t)MM * DD];   // tf32-rounded ins
__device__ __align__(16) float  g_Wi32[(size_t)DD * ND];    // tf32-rounded W_i
__device__ __align__(16) float  g_hx[2][BB * DD];           // exact h_eff ping-pong
__device__ float4               g_hf[2][BB * DD / 4];       // frag-ordered tf32 h ping-pong
__device__ unsigned             g_flags[NBLK * 32];         // barrier flags (128B apart)
__device__ unsigned             g_release;                  // barrier release word

__device__ __forceinline__ float to_tf32(float x) {
    float y;
    asm("cvt.rna.tf32.f32 %0, %1;" : "=f"(y) : "f"(x));
    return y;
}

__device__ __forceinline__ unsigned ld_acq(const unsigned* p) {
    unsigned v;
    asm volatile("ld.acquire.gpu.global.u32 %0, [%1];" : "=r"(v) : "l"(p) : "memory");
    return v;
}
__device__ __forceinline__ void st_rel(unsigned* p, unsigned v) {
    asm volatile("st.release.gpu.global.u32 [%0], %1;" :: "l"(p), "r"(v) : "memory");
}

__device__ __forceinline__ void mma_au(float d[4], const unsigned a[4],
                                       unsigned b0, unsigned b1) {
    asm volatile("mma.sync.aligned.m16n8k8.row.col.f32.tf32.tf32.f32 "
                 "{%0,%1,%2,%3}, {%4,%5,%6,%7}, {%8,%9}, {%0,%1,%2,%3};"
                 : "+f"(d[0]), "+f"(d[1]), "+f"(d[2]), "+f"(d[3])
                 : "r"(a[0]), "r"(a[1]), "r"(a[2]), "r"(a[3]),
                   "r"(b0), "r"(b1));
}

__device__ __forceinline__ void mma_f4(float d[4], const float4& a, const float2& b) {
    unsigned av[4] = {__float_as_uint(a.x), __float_as_uint(a.y),
                      __float_as_uint(a.z), __float_as_uint(a.w)};
    mma_au(d, av, __float_as_uint(b.x), __float_as_uint(b.y));
}

__device__ __forceinline__ void cp16(const void* smem_dst, const float* src) {
    unsigned d = (unsigned)__cvta_generic_to_shared(smem_dst);
    asm volatile("cp.async.cg.shared.global [%0], [%1], 16;" :: "r"(d), "l"(src));
}
__device__ __forceinline__ void cp_commit() {
    asm volatile("cp.async.commit_group;" ::: "memory");
}

// frag-order offset (floats) of h[b][k] inside one g_hf buffer:
// layout [ks(128)][mt(4)][lane(32)] float4
__device__ __forceinline__ int frag_off(int b, int k) {
    int mt = b >> 4, r = b & 15, q = r & 7, rh = r >> 3;
    int ks = k >> 3, kk = k & 7, tg = kk & 3, khf = kk >> 2;
    return (((ks * 4 + mt) * 32) + (q * 4 + tg)) * 4 + (rh + 2 * khf);
}

// ---------------------------------------------------------------------------
// prep: tf32-round ins + W_i; build step-0 h (done-masked) exact + frag;
// zero barrier state.
// ---------------------------------------------------------------------------
__global__ void prep(const float* __restrict__ ins,
                     const float* __restrict__ W_i,
                     const float* __restrict__ hiddens,
                     const int*   __restrict__ dones,
                     const float* __restrict__ init_carry) {
    size_t i0 = (size_t)blockIdx.x * blockDim.x + threadIdx.x;
    size_t stride = (size_t)gridDim.x * blockDim.x;

    const float4* s1 = (const float4*)ins;
    float4* d1 = (float4*)g_ins32;
    for (size_t i = i0; i < (size_t)MM * DD / 4; i += stride) {
        float4 v = s1[i];
        v.x = to_tf32(v.x); v.y = to_tf32(v.y);
        v.z = to_tf32(v.z); v.w = to_tf32(v.w);
        d1[i] = v;
    }
    const float4* s2 = (const float4*)W_i;
    float4* d2 = (float4*)g_Wi32;
    for (size_t i = i0; i < (size_t)DD * ND / 4; i += stride) {
        float4 v = s2[i];
        v.x = to_tf32(v.x); v.y = to_tf32(v.y);
        v.z = to_tf32(v.z); v.w = to_tf32(v.w);
        d2[i] = v;
    }
    for (size_t i = i0; i < (size_t)BB * DD; i += stride) {
        int b = (int)(i >> 10), d = (int)(i & 1023);
        float v = dones[b] ? hiddens[i] : init_carry[i];
        g_hx[0][i] = v;
        ((float*)g_hf[0])[frag_off(b, d)] = to_tf32(v);
    }
    if (i0 < NBLK) g_flags[i0 * 32] = 0u;
    if (i0 == 0) g_release = 0u;
}

// ---------------------------------------------------------------------------
// x_proj GEMM: C = g_ins32 * g_Wi32 + b_i.  128x128 tile, BK=32, cp.async
// double-buffered. 256 thr = 8 warps (2 wm x 4 wn), warp tile 64x32.
// occupancy 2 blocks/SM (69KB smem each) to hide L2/DRAM latency.
// ---------------------------------------------------------------------------
#define GA_ST 4608   // 128*36 floats per A stage
#define GB_ST 4224   // 32*132 floats per B stage
#define GEMM_SMEM ((2*GA_ST + 2*GB_ST) * 4)

__global__ void __launch_bounds__(256, 2)
gemm_xproj(const float* __restrict__ bias) {
    extern __shared__ float sm[];
    float* As = sm;
    float* Bs = sm + 2 * GA_ST;

    const int tid  = threadIdx.x;
    const int w    = tid >> 5, lane = tid & 31;
    const int q    = lane >> 2, tg = lane & 3;
    const int wm   = w >> 2, wn = w & 3;
    const int bm   = blockIdx.y * 128;
    const int bn   = blockIdx.x * 128;

    float acc[16][4];
    #pragma unroll
    for (int i = 0; i < 16; i++)
        #pragma unroll
        for (int j = 0; j < 4; j++) acc[i][j] = 0.f;

    #define LOAD_STAGE(st, kc)                                                  \
    {                                                                           \
        _Pragma("unroll")                                                       \
        for (int l = 0; l < 4; l++) {                                           \
            int e = tid + l * 256; int r = e >> 3, c4 = e & 7;                  \
            cp16(&As[(st) * GA_ST + r * 36 + c4 * 4],                           \
                 &g_ins32[(size_t)(bm + r) * DD + (kc) + c4 * 4]);              \
        }                                                                       \
        _Pragma("unroll")                                                       \
        for (int l = 0; l < 4; l++) {                                           \
            int e = tid + l * 256; int r = e >> 5, c4 = e & 31;                 \
            cp16(&Bs[(st) * GB_ST + r * 132 + c4 * 4],                          \
                 &g_Wi32[(size_t)((kc) + r) * ND + bn + c4 * 4]);               \
        }                                                                       \
        cp_commit();                                                            \
    }

    LOAD_STAGE(0, 0)

    for (int itk = 0; itk < DD / 32; itk++) {
        if (itk + 1 < DD / 32) {
            LOAD_STAGE((itk + 1) & 1, (itk + 1) * 32)
            asm volatile("cp.async.wait_group 1;" ::: "memory");
        } else {
            asm volatile("cp.async.wait_group 0;" ::: "memory");
        }
        __syncthreads();

        const float* as = &As[(itk & 1) * GA_ST];
        const float* bs = &Bs[(itk & 1) * GB_ST];

        #pragma unroll
        for (int ks = 0; ks < 4; ks++) {
            const int koff = ks * 8;
            unsigned a[4][4];
            #pragma unroll
            for (int mt = 0; mt < 4; mt++) {
                int r0 = wm * 64 + mt * 16 + q;
                a[mt][0] = __float_as_uint(as[r0 * 36 + koff + tg]);
                a[mt][1] = __float_as_uint(as[(r0 + 8) * 36 + koff + tg]);
                a[mt][2] = __float_as_uint(as[r0 * 36 + koff + tg + 4]);
                a[mt][3] = __float_as_uint(as[(r0 + 8) * 36 + koff + tg + 4]);
            }
            #pragma unroll
            for (int nt = 0; nt < 4; nt++) {
                int n = wn * 32 + nt * 8 + q;
                unsigned b0 = __float_as_uint(bs[(koff + tg) * 132 + n]);
                unsigned b1 = __float_as_uint(bs[(koff + tg + 4) * 132 + n]);
                #pragma unroll
                for (int mt = 0; mt < 4; mt++)
                    mma_au(acc[mt * 4 + nt], a[mt], b0, b1);
            }
        }
        __syncthreads();
    }

    #pragma unroll
    for (int mt = 0; mt < 4; mt++) {
        int row = bm + wm * 64 + mt * 16 + q;
        #pragma unroll
        for (int nt = 0; nt < 4; nt++) {
            int col = bn + wn * 32 + nt * 8 + 2 * tg;
            float2 bb = *(const float2*)&bias[col];
            float* c = acc[mt * 4 + nt];
            float2 v0 = make_float2(c[0] + bb.x, c[1] + bb.y);
            float2 v1 = make_float2(c[2] + bb.x, c[3] + bb.y);
            *(float2*)&g_xproj[(size_t)row * ND + col] = v0;
            *(float2*)&g_xproj[(size_t)(row + 8) * ND + col] = v1;
        }
    }
}

// ---------------------------------------------------------------------------
// Persistent GRU scan. grid=128 (1/SM), block=256. Block owns 8 d-cols
// (24 gate cols). W_h slice frag-ordered in smem (96KB). k-split 8 across
// warps. A-frags: direct LDG.128 (L2-only) from frag-ordered g_hf ping-pong,
// depth-4 software pipeline. 4-slab smem reduction, float2 gate epilogue
// (writes next step's done-masked h exact + frag-tf32). Flag-array grid
// barrier per step (parallel arrivals, block-0 aggregation + single release).
//
// smem floats: Wf [ksg=128][nt=3][lane=32]x2 = 24576 ; Red 4*64*24 = 6144
// ---------------------------------------------------------------------------
#define SCAN_SMEM ((24576 + 6144) * 4)

__global__ void __launch_bounds__(256, 1)
gru_scan(const float* __restrict__ hiddens,
         const int*   __restrict__ dones,
         const float* __restrict__ W_h,
         const float* __restrict__ b_hn,
         float* __restrict__ out) {
    extern __shared__ float smem[];
    float* Wf  = smem;             // 24576 floats
    float* Red = smem + 24576;     // 6144 floats

    const int tid  = threadIdx.x;
    const int bid  = blockIdx.x;
    const int w    = tid >> 5;
    const int lane = tid & 31;
    const int q    = lane >> 2;
    const int tg   = lane & 3;
    const int d0   = bid * 8;
    const int ksg0 = w * 16;             // warp's first k-group (k-split 8)

    // ---- one-time: build frag-ordered W (tf32) ----
    for (int idx = tid; idx < 24576; idx += 256) {
        int hh = idx & 1, p = idx >> 1;
        int ln = p & 31, rest = p >> 5;
        int nt = rest % 3, ksg = rest / 3;
        int qq = ln >> 2, tt = ln & 3;
        int k  = ksg * 8 + tt + hh * 4;
        Wf[idx] = to_tf32(W_h[(size_t)k * ND + nt * DD + d0 + qq]);
    }
    __syncthreads();

    // epilogue-fixed indices: thread owns (b=pb, d=pd, pd+1)
    const int pb = tid >> 2;
    const int pd = d0 + ((tid * 2) & 7);
    const float bh0 = b_hn[pd], bh1 = b_hn[pd + 1];
    const int fo0 = frag_off(pb, pd);
    const int fo1 = frag_off(pb, pd + 1);

    for (int t = 0; t < TT; t++) {
        const int par = t & 1;

        // ---- early loads for epilogue (latency hidden under k-loop) ----
        size_t tb = (size_t)t * BB + pb;
        float2 xr = *(const float2*)&g_xproj[tb * ND + pd];
        float2 xz = *(const float2*)&g_xproj[tb * ND + DD + pd];
        float2 xn = *(const float2*)&g_xproj[tb * ND + 2 * DD + pd];
        float2 he = __ldcg((const float2*)&g_hx[par][pb * DD + pd]);
        float2 hv = make_float2(0.f, 0.f);
        int dn = 0;
        if (t + 1 < TT) {
            hv = *(const float2*)&hiddens[((size_t)(t + 1) * BB + pb) * DD + pd];
            dn = dones[(t + 1) * BB + pb];
        }

        // ---- k loop: 16 k-groups per warp, A-frag LDG pipeline depth 4 ----
        const float4* hf = g_hf[par];
        float4 pre[4][4];
        #pragma unroll
        for (int i = 0; i < 4; i++)
            #pragma unroll
            for (int mt = 0; mt < 4; mt++)
                pre[i][mt] = __ldcg(&hf[((ksg0 + i) * 4 + mt) * 32 + lane]);

        float acc[12][4];
        #pragma unroll
        for (int i = 0; i < 12; i++)
            #pragma unroll
            for (int j = 0; j < 4; j++) acc[i][j] = 0.f;

        const float2* Wf2 = (const float2*)Wf;
        #pragma unroll
        for (int it = 0; it < 16; it++) {
            const int slot = it & 3;
            float2 bv0 = Wf2[((ksg0 + it) * 3 + 0) * 32 + lane];
            float2 bv1 = Wf2[((ksg0 + it) * 3 + 1) * 32 + lane];
            float2 bv2 = Wf2[((ksg0 + it) * 3 + 2) * 32 + lane];
            #pragma unroll
            for (int mt = 0; mt < 4; mt++) {
                mma_f4(acc[mt * 3 + 0], pre[slot][mt], bv0);
                mma_f4(acc[mt * 3 + 1], pre[slot][mt], bv1);
                mma_f4(acc[mt * 3 + 2], pre[slot][mt], bv2);
            }
            if (it + 4 < 16) {
                #pragma unroll
                for (int mt = 0; mt < 4; mt++)
                    pre[slot][mt] = __ldcg(&hf[((ksg0 + it + 4) * 4 + mt) * 32 + lane]);
            }
        }

        // ---- reduce 8 warp partials -> 4 slabs ----
        float* slab = &Red[(w & 3) * 1536];
        if (w >= 4) {
            #pragma unroll
            for (int tI = 0; tI < 12; tI++) {
                int mt = tI / 3, nt = tI - mt * 3;
                int base = (mt * 16 + q) * 24 + nt * 8 + 2 * tg;
                slab[base]           = acc[tI][0];
                slab[base + 1]       = acc[tI][1];
                slab[base + 192]     = acc[tI][2];
                slab[base + 193]     = acc[tI][3];
            }
        }
        __syncthreads();
        if (w < 4) {
            #pragma unroll
            for (int tI = 0; tI < 12; tI++) {
                int mt = tI / 3, nt = tI - mt * 3;
                int base = (mt * 16 + q) * 24 + nt * 8 + 2 * tg;
                slab[base]       += acc[tI][0];
                slab[base + 1]   += acc[tI][1];
                slab[base + 192] += acc[tI][2];
                slab[base + 193] += acc[tI][3];
            }
        }
        __syncthreads();

        // ---- gate epilogue (2 adjacent d per thread) ----
        {
            const int di = (tid * 2) & 7;
            float s0r = 0.f, s0z = 0.f, s0n = 0.f;
            float s1r = 0.f, s1z = 0.f, s1n = 0.f;
            #pragma unroll
            for (int s = 0; s < 4; s++) {
                const float* rb = &Red[s * 1536 + pb * 24];
                s0r += rb[di];      s1r += rb[di + 1];
                s0z += rb[8 + di];  s1z += rb[8 + di + 1];
                s0n += rb[16 + di]; s1n += rb[16 + di + 1];
            }

            float r0 = 1.f / (1.f + __expf(-(xr.x + s0r)));
            float z0 = 1.f / (1.f + __expf(-(xz.x + s0z)));
            float n0 = tanhf(xn.x + r0 * (s0n + bh0));
            float h0 = (1.f - z0) * n0 + z0 * he.x;

            float r1 = 1.f / (1.f + __expf(-(xr.y + s1r)));
            float z1 = 1.f / (1.f + __expf(-(xz.y + s1z)));
            float n1 = tanhf(xn.y + r1 * (s1n + bh1));
            float h1 = (1.f - z1) * n1 + z1 * he.y;

            *(float2*)&out[(size_t)BB * DD + tb * DD + pd] = make_float2(h0, h1);
            if (t == TT - 1)
                *(float2*)&out[(size_t)pb * DD + pd] = make_float2(h0, h1);

            // next-step h_eff (done-masked), exact + frag-tf32
            float v0 = dn ? hv.x : h0;
            float v1 = dn ? hv.y : h1;
            *(float2*)&g_hx[par ^ 1][pb * DD + pd] = make_float2(v0, v1);
            float* hfn = (float*)g_hf[par ^ 1];
            hfn[fo0] = to_tf32(v0);
            hfn[fo1] = to_tf32(v1);
        }

        if (t == TT - 1) break;   // nothing to synchronize after last step

        // ---- flag-array grid barrier ----
        __threadfence();
        __syncthreads();
        const unsigned tgt = (unsigned)(t + 1);
        if (tid == 0) st_rel(&g_flags[bid * 32], tgt);
        if (bid == 0) {
            if (tid < NBLK) {
                while (ld_acq(&g_flags[tid * 32]) < tgt) {}
            }
            __syncthreads();
            if (tid == 0) st_rel(&g_release, tgt);
        } else {
            if (tid == 0) {
                while (ld_acq(&g_release) < tgt) {}
            }
        }
        __syncthreads();
    }
}

// ---------------------------------------------------------------------------
extern "C" void kernel_launch(void* const* d_in, const int* in_sizes, int n_in,
                              void* d_out, int out_size) {
    const float* ins        = (const float*)d_in[0];
    const float* hiddens    = (const float*)d_in[1];
    const int*   dones      = (const int*)d_in[2];
    const float* init_carry = (const float*)d_in[3];
    const float* W_i        = (const float*)d_in[4];
    const float* W_h        = (const float*)d_in[5];
    const float* b_i        = (const float*)d_in[6];
    const float* b_hn       = (const float*)d_in[7];
    float* out = (float*)d_out;

    static int attr_set = 0;
    if (!attr_set) {
        cudaFuncSetAttribute(gemm_xproj, cudaFuncAttributeMaxDynamicSharedMemorySize,
                             GEMM_SMEM);
        cudaFuncSetAttribute(gru_scan, cudaFuncAttributeMaxDynamicSharedMemorySize,
                             SCAN_SMEM);
        attr_set = 1;
    }

    prep<<<2048, 256>>>(ins, W_i, hiddens, dones, init_carry);

    dim3 grid_gemm(ND / 128, MM / 128);   // 24 x 128
    gemm_xproj<<<grid_gemm, 256, GEMM_SMEM>>>(b_i);

    gru_scan<<<NBLK, 256, SCAN_SMEM>>>(hiddens, dones, W_h, b_hn, out);
}

// round 12
// speedup vs baseline: 1.4323x; 1.2268x over previous
#include <cuda_runtime.h>
#include <cuda_fp16.h>
#include <math.h>
#include <stdint.h>

#define TT 256
#define BB 64
#define DD 1024
#define ND 3072          // 3*D
#define MM (TT*BB)       // 16384
#define NBLK 128         // scan blocks; each owns 8 d-cols

// ---------------- device scratch (no cudaMalloc allowed) -------------------
__device__ __align__(16) float  g_xproj[(size_t)MM * ND];   // [T*B, 3D]
__device__ __align__(16) float  g_ins32[(size_t)MM * DD];   // tf32-rounded ins
__device__ __align__(16) float  g_Wi32[(size_t)DD * ND];    // tf32-rounded W_i
__device__ float4               g_hfh[2][BB * DD / 8];      // frag-ordered fp16 h ping-pong
__device__ unsigned             g_ctr;                      // grid barrier counter

__device__ __forceinline__ float to_tf32(float x) {
    float y;
    asm("cvt.rna.tf32.f32 %0, %1;" : "=f"(y) : "f"(x));
    return y;
}

// tf32 mma (gemm_xproj only)
__device__ __forceinline__ void mma_au(float d[4], const unsigned a[4],
                                       unsigned b0, unsigned b1) {
    asm volatile("mma.sync.aligned.m16n8k8.row.col.f32.tf32.tf32.f32 "
                 "{%0,%1,%2,%3}, {%4,%5,%6,%7}, {%8,%9}, {%0,%1,%2,%3};"
                 : "+f"(d[0]), "+f"(d[1]), "+f"(d[2]), "+f"(d[3])
                 : "r"(a[0]), "r"(a[1]), "r"(a[2]), "r"(a[3]),
                   "r"(b0), "r"(b1));
}

// fp16 mma m16n8k16, fp32 accum (scan)
__device__ __forceinline__ void mma_h16(float d[4], const float4& a, const uint2& b) {
    unsigned a0 = __float_as_uint(a.x), a1 = __float_as_uint(a.y);
    unsigned a2 = __float_as_uint(a.z), a3 = __float_as_uint(a.w);
    asm volatile("mma.sync.aligned.m16n8k16.row.col.f32.f16.f16.f32 "
                 "{%0,%1,%2,%3}, {%4,%5,%6,%7}, {%8,%9}, {%0,%1,%2,%3};"
                 : "+f"(d[0]), "+f"(d[1]), "+f"(d[2]), "+f"(d[3])
                 : "r"(a0), "r"(a1), "r"(a2), "r"(a3),
                   "r"(b.x), "r"(b.y));
}

__device__ __forceinline__ void cp16(const void* smem_dst, const float* src) {
    unsigned d = (unsigned)__cvta_generic_to_shared(smem_dst);
    asm volatile("cp.async.cg.shared.global [%0], [%1], 16;" :: "r"(d), "l"(src));
}
__device__ __forceinline__ void cp_commit() {
    asm volatile("cp.async.commit_group;" ::: "memory");
}

// fp16 frag layout: [ksg(64 k16-groups)][mt(4)][lane(32)] x 4 half2 regs.
// reg r holds (row q + 8*rh, k pair) where r = rh + 2*khalf;
// half2 index of h[b][k-pair kp]:
__device__ __forceinline__ int frag_off_h2(int b, int kp) {
    int k = kp * 2;
    int ksg = k >> 4, klo = k & 15;
    int tg = (klo >> 1) & 3, khalf = klo >> 3;
    int mt = b >> 4, r = b & 15, q = r & 7, rh = r >> 3;
    int reg = rh + 2 * khalf;
    return (((ksg * 4 + mt) * 32) + (q * 4 + tg)) * 4 + reg;
}

// ---------------------------------------------------------------------------
// prep: tf32-round ins + W_i (gemm operands); build step-0 h_eff (done-masked)
// in fp16 frag order; reset grid counter.
// ---------------------------------------------------------------------------
__global__ void prep(const float* __restrict__ ins,
                     const float* __restrict__ W_i,
                     const float* __restrict__ hiddens,
                     const int*   __restrict__ dones,
                     const float* __restrict__ init_carry) {
    size_t i0 = (size_t)blockIdx.x * blockDim.x + threadIdx.x;
    size_t stride = (size_t)gridDim.x * blockDim.x;

    const float4* s1 = (const float4*)ins;
    float4* d1 = (float4*)g_ins32;
    for (size_t i = i0; i < (size_t)MM * DD / 4; i += stride) {
        float4 v = s1[i];
        v.x = to_tf32(v.x); v.y = to_tf32(v.y);
        v.z = to_tf32(v.z); v.w = to_tf32(v.w);
        d1[i] = v;
    }
    const float4* s2 = (const float4*)W_i;
    float4* d2 = (float4*)g_Wi32;
    for (size_t i = i0; i < (size_t)DD * ND / 4; i += stride) {
        float4 v = s2[i];
        v.x = to_tf32(v.x); v.y = to_tf32(v.y);
        v.z = to_tf32(v.z); v.w = to_tf32(v.w);
        d2[i] = v;
    }
    // step-0 h_eff in fp16 frag order (pairwise)
    __half2* hf = (__half2*)g_hfh[0];
    for (size_t i = i0; i < (size_t)BB * DD / 2; i += stride) {
        int b  = (int)(i >> 9);          // /512 pairs per row
        int kp = (int)(i & 511);
        size_t base = (size_t)b * DD + kp * 2;
        const float* src = dones[b] ? &hiddens[base] : &init_carry[base];
        hf[frag_off_h2(b, kp)] = __floats2half2_rn(src[0], src[1]);
    }
    if (i0 == 0) g_ctr = 0u;
}

// ---------------------------------------------------------------------------
// x_proj GEMM: C = g_ins32 * g_Wi32 + b_i.  128x128 tile, BK=32, cp.async
// double-buffered. 256 thr = 8 warps (2 wm x 4 wn), warp tile 64x32.
// (unchanged from R6 best)
// ---------------------------------------------------------------------------
#define GA_ST 4608   // 128*36 floats per A stage
#define GB_ST 4224   // 32*132 floats per B stage
#define GEMM_SMEM ((2*GA_ST + 2*GB_ST) * 4)

__global__ void __launch_bounds__(256, 1)
gemm_xproj(const float* __restrict__ bias) {
    extern __shared__ float sm[];
    float* As = sm;
    float* Bs = sm + 2 * GA_ST;

    const int tid  = threadIdx.x;
    const int w    = tid >> 5, lane = tid & 31;
    const int q    = lane >> 2, tg = lane & 3;
    const int wm   = w >> 2, wn = w & 3;
    const int bm   = blockIdx.y * 128;
    const int bn   = blockIdx.x * 128;

    float acc[16][4];
    #pragma unroll
    for (int i = 0; i < 16; i++)
        #pragma unroll
        for (int j = 0; j < 4; j++) acc[i][j] = 0.f;

    #define LOAD_STAGE(st, kc)                                                  \
    {                                                                           \
        _Pragma("unroll")                                                       \
        for (int l = 0; l < 4; l++) {                                           \
            int e = tid + l * 256; int r = e >> 3, c4 = e & 7;                  \
            cp16(&As[(st) * GA_ST + r * 36 + c4 * 4],                           \
                 &g_ins32[(size_t)(bm + r) * DD + (kc) + c4 * 4]);              \
        }                                                                       \
        _Pragma("unroll")                                                       \
        for (int l = 0; l < 4; l++) {                                           \
            int e = tid + l * 256; int r = e >> 5, c4 = e & 31;                 \
            cp16(&Bs[(st) * GB_ST + r * 132 + c4 * 4],                          \
                 &g_Wi32[(size_t)((kc) + r) * ND + bn + c4 * 4]);               \
        }                                                                       \
        cp_commit();                                                            \
    }

    LOAD_STAGE(0, 0)

    for (int itk = 0; itk < DD / 32; itk++) {
        if (itk + 1 < DD / 32) {
            LOAD_STAGE((itk + 1) & 1, (itk + 1) * 32)
            asm volatile("cp.async.wait_group 1;" ::: "memory");
        } else {
            asm volatile("cp.async.wait_group 0;" ::: "memory");
        }
        __syncthreads();

        const float* as = &As[(itk & 1) * GA_ST];
        const float* bs = &Bs[(itk & 1) * GB_ST];

        #pragma unroll
        for (int ks = 0; ks < 4; ks++) {
            const int koff = ks * 8;
            unsigned a[4][4];
            #pragma unroll
            for (int mt = 0; mt < 4; mt++) {
                int r0 = wm * 64 + mt * 16 + q;
                a[mt][0] = __float_as_uint(as[r0 * 36 + koff + tg]);
                a[mt][1] = __float_as_uint(as[(r0 + 8) * 36 + koff + tg]);
                a[mt][2] = __float_as_uint(as[r0 * 36 + koff + tg + 4]);
                a[mt][3] = __float_as_uint(as[(r0 + 8) * 36 + koff + tg + 4]);
            }
            #pragma unroll
            for (int nt = 0; nt < 4; nt++) {
                int n = wn * 32 + nt * 8 + q;
                unsigned b0 = __float_as_uint(bs[(koff + tg) * 132 + n]);
                unsigned b1 = __float_as_uint(bs[(koff + tg + 4) * 132 + n]);
                #pragma unroll
                for (int mt = 0; mt < 4; mt++)
                    mma_au(acc[mt * 4 + nt], a[mt], b0, b1);
            }
        }
        __syncthreads();
    }

    #pragma unroll
    for (int mt = 0; mt < 4; mt++) {
        int row = bm + wm * 64 + mt * 16 + q;
        #pragma unroll
        for (int nt = 0; nt < 4; nt++) {
            int col = bn + wn * 32 + nt * 8 + 2 * tg;
            float2 bb = *(const float2*)&bias[col];
            float* c = acc[mt * 4 + nt];
            float2 v0 = make_float2(c[0] + bb.x, c[1] + bb.y);
            float2 v1 = make_float2(c[2] + bb.x, c[3] + bb.y);
            *(float2*)&g_xproj[(size_t)row * ND + col] = v0;
            *(float2*)&g_xproj[(size_t)(row + 8) * ND + col] = v1;
        }
    }
}

// ---------------------------------------------------------------------------
// Persistent GRU scan (fp16 m16n8k16). grid=128 (1/SM), block=256. Block owns
// 8 d-cols (24 gate cols). W_h slice fp16 frag-ordered in smem (48KB).
// k-split 8 across warps: each warp 8 k16-groups. A-frags: one LDG.128
// (L2-only) per (group, m-tile) from fp16 frag-ordered g_hfh ping-pong,
// depth-3 software pipeline. Exact h carry lives in REGISTERS (thread owns
// fixed (b,d) across steps). 4-slab smem reduction, fused gate epilogue,
// atomic-counter grid barrier per step.
//
// smem: Wh fp16 [ksg64][nt3][lane32] x uint2 = 49152 B ; Red 6144 fl = 24576 B
// ---------------------------------------------------------------------------
#define SCAN_SMEM (49152 + 24576)

__global__ void __launch_bounds__(256, 1)
gru_scan(const float* __restrict__ hiddens,
         const int*   __restrict__ dones,
         const float* __restrict__ init_carry,
         const float* __restrict__ W_h,
         const float* __restrict__ b_hn,
         float* __restrict__ out) {
    extern __shared__ float smem[];
    uint2* Wh  = (uint2*)smem;                 // 6144 uint2 (49152 B)
    float* Red = smem + 12288;                 // 6144 floats

    const int tid  = threadIdx.x;
    const int w    = tid >> 5;
    const int lane = tid & 31;
    const int q    = lane >> 2;
    const int tg   = lane & 3;
    const int d0   = blockIdx.x * 8;
    const int ksg0 = w * 8;              // warp's first k16-group (k-split 8)

    // ---- one-time: build fp16 frag-ordered W slice ----
    // half2 entry idx: ((ksg*3+nt)*32+lane)*2 + breg
    // breg b covers k = ksg*16 + 2*tg + 8*breg (+1), col = nt*DD + d0 + q
    for (int idx = tid; idx < 12288; idx += 256) {
        int breg = idx & 1, l2 = idx >> 1;
        int ln = l2 & 31, rest = l2 >> 5;
        int nt = rest % 3, ksg = rest / 3;
        int qq = ln >> 2, tt = ln & 3;
        int k  = ksg * 16 + 2 * tt + 8 * breg;
        size_t col = (size_t)nt * DD + d0 + qq;
        ((__half2*)Wh)[idx] = __floats2half2_rn(W_h[(size_t)k * ND + col],
                                                W_h[(size_t)(k + 1) * ND + col]);
    }
    __syncthreads();

    // epilogue-fixed indices: thread owns (b=pb, d=pd, pd+1); pd-d0 even
    const int pb = tid >> 2;
    const int pd = d0 + ((tid * 2) & 7);
    const float bh0 = b_hn[pd], bh1 = b_hn[pd + 1];
    const int foh = frag_off_h2(pb, pd >> 1);

    // exact h_eff carry in registers; init = step-0 masked value
    float2 he;
    {
        size_t base = (size_t)pb * DD + pd;
        he = dones[pb] ? *(const float2*)&hiddens[base]
                       : *(const float2*)&init_carry[base];
    }

    for (int t = 0; t < TT; t++) {
        const int par = t & 1;

        // ---- early loads for epilogue (latency hidden under k-loop) ----
        size_t tb = (size_t)t * BB + pb;
        float2 xr = *(const float2*)&g_xproj[tb * ND + pd];
        float2 xz = *(const float2*)&g_xproj[tb * ND + DD + pd];
        float2 xn = *(const float2*)&g_xproj[tb * ND + 2 * DD + pd];
        float2 hv = make_float2(0.f, 0.f);
        int dn = 0;
        if (t + 1 < TT) {
            hv = *(const float2*)&hiddens[((size_t)(t + 1) * BB + pb) * DD + pd];
            dn = dones[(t + 1) * BB + pb];
        }

        // ---- k loop: 8 k16-groups per warp, A-frag LDG pipeline depth 3 ----
        const float4* hf = g_hfh[par];
        float4 pre[3][4];
        #pragma unroll
        for (int i = 0; i < 3; i++)
            #pragma unroll
            for (int mt = 0; mt < 4; mt++)
                pre[i][mt] = __ldcg(&hf[((ksg0 + i) * 4 + mt) * 32 + lane]);

        float acc[12][4];
        #pragma unroll
        for (int i = 0; i < 12; i++)
            #pragma unroll
            for (int j = 0; j < 4; j++) acc[i][j] = 0.f;

        #pragma unroll
        for (int it = 0; it < 8; it++) {
            const int slot = it % 3;
            uint2 bv0 = Wh[((ksg0 + it) * 3 + 0) * 32 + lane];
            uint2 bv1 = Wh[((ksg0 + it) * 3 + 1) * 32 + lane];
            uint2 bv2 = Wh[((ksg0 + it) * 3 + 2) * 32 + lane];
            #pragma unroll
            for (int mt = 0; mt < 4; mt++) {
                mma_h16(acc[mt * 3 + 0], pre[slot][mt], bv0);
                mma_h16(acc[mt * 3 + 1], pre[slot][mt], bv1);
                mma_h16(acc[mt * 3 + 2], pre[slot][mt], bv2);
            }
            if (it + 3 < 8) {
                #pragma unroll
                for (int mt = 0; mt < 4; mt++)
                    pre[slot][mt] = __ldcg(&hf[((ksg0 + it + 3) * 4 + mt) * 32 + lane]);
            }
        }

        // ---- reduce 8 warp partials -> 4 slabs ----
        float* slab = &Red[(w & 3) * 1536];
        if (w >= 4) {
            #pragma unroll
            for (int tI = 0; tI < 12; tI++) {
                int mt = tI / 3, nt = tI - mt * 3;
                int base = (mt * 16 + q) * 24 + nt * 8 + 2 * tg;
                slab[base]           = acc[tI][0];
                slab[base + 1]       = acc[tI][1];
                slab[base + 192]     = acc[tI][2];
                slab[base + 193]     = acc[tI][3];
            }
        }
        __syncthreads();
        if (w < 4) {
            #pragma unroll
            for (int tI = 0; tI < 12; tI++) {
                int mt = tI / 3, nt = tI - mt * 3;
                int base = (mt * 16 + q) * 24 + nt * 8 + 2 * tg;
                slab[base]       += acc[tI][0];
                slab[base + 1]   += acc[tI][1];
                slab[base + 192] += acc[tI][2];
                slab[base + 193] += acc[tI][3];
            }
        }
        __syncthreads();

        // ---- gate epilogue (2 adjacent d per thread) ----
        {
            const int di = (tid * 2) & 7;
            float s0r = 0.f, s0z = 0.f, s0n = 0.f;
            float s1r = 0.f, s1z = 0.f, s1n = 0.f;
            #pragma unroll
            for (int s = 0; s < 4; s++) {
                const float* rb = &Red[s * 1536 + pb * 24];
                s0r += rb[di];      s1r += rb[di + 1];
                s0z += rb[8 + di];  s1z += rb[8 + di + 1];
                s0n += rb[16 + di]; s1n += rb[16 + di + 1];
            }

            float r0 = 1.f / (1.f + __expf(-(xr.x + s0r)));
            float z0 = 1.f / (1.f + __expf(-(xz.x + s0z)));
            float n0 = tanhf(xn.x + r0 * (s0n + bh0));
            float h0 = (1.f - z0) * n0 + z0 * he.x;

            float r1 = 1.f / (1.f + __expf(-(xr.y + s1r)));
            float z1 = 1.f / (1.f + __expf(-(xz.y + s1z)));
            float n1 = tanhf(xn.y + r1 * (s1n + bh1));
            float h1 = (1.f - z1) * n1 + z1 * he.y;

            *(float2*)&out[(size_t)BB * DD + tb * DD + pd] = make_float2(h0, h1);
            if (t == TT - 1)
                *(float2*)&out[(size_t)pb * DD + pd] = make_float2(h0, h1);

            // next-step h_eff (done-masked): registers + fp16 frag store
            he.x = dn ? hv.x : h0;
            he.y = dn ? hv.y : h1;
            ((__half2*)g_hfh[par ^ 1])[foh] = __floats2half2_rn(he.x, he.y);
        }

        if (t == TT - 1) break;

        // ---- grid barrier ----
        __threadfence();
        __syncthreads();
        if (tid == 0) {
            atomicAdd(&g_ctr, 1u);
            const unsigned target = (unsigned)(t + 1) * NBLK;
            unsigned vv;
            do {
                asm volatile("ld.acquire.gpu.global.u32 %0, [%1];"
                             : "=r"(vv) : "l"(&g_ctr) : "memory");
            } while (vv < target);
        }
        __syncthreads();
    }
}

// ---------------------------------------------------------------------------
extern "C" void kernel_launch(void* const* d_in, const int* in_sizes, int n_in,
                              void* d_out, int out_size) {
    const float* ins        = (const float*)d_in[0];
    const float* hiddens    = (const float*)d_in[1];
    const int*   dones      = (const int*)d_in[2];
    const float* init_carry = (const float*)d_in[3];
    const float* W_i        = (const float*)d_in[4];
    const float* W_h        = (const float*)d_in[5];
    const float* b_i        = (const float*)d_in[6];
    const float* b_hn       = (const float*)d_in[7];
    float* out = (float*)d_out;

    static int attr_set = 0;
    if (!attr_set) {
        cudaFuncSetAttribute(gemm_xproj, cudaFuncAttributeMaxDynamicSharedMemorySize,
                             GEMM_SMEM);
        cudaFuncSetAttribute(gru_scan, cudaFuncAttributeMaxDynamicSharedMemorySize,
                             SCAN_SMEM);
        attr_set = 1;
    }

    prep<<<2048, 256>>>(ins, W_i, hiddens, dones, init_carry);

    dim3 grid_gemm(ND / 128, MM / 128);   // 24 x 128
    gemm_xproj<<<grid_gemm, 256, GEMM_SMEM>>>(b_i);

    gru_scan<<<NBLK, 256, SCAN_SMEM>>>(hiddens, dones, init_carry, W_h, b_hn, out);
}